// round 14
// baseline (speedup 1.0000x reference)
#include <cuda_runtime.h>
#include <cuda_fp16.h>
#include <cstdint>

#define B_    8
#define T_    4096
#define R_    1024
#define F_    64
#define I_    32
#define KTOT  96            // F_ + I_
#define NBLK  128           // scan blocks (8 rows of W_hh each)
#define NTHR  256

// ---------------- device scratch (no allocations allowed) ----------------
// hidden state in fp16: [buf][k][b], one 16B row per k (all 8 batches)
__device__ __align__(16) __half g_h[2][R_][B_];
__device__ __align__(128) unsigned g_flag[NBLK * 32];  // 1 epoch flag per CTA, private line

// ---------------- helpers ----------------
__device__ __forceinline__ unsigned long long pack2(float a, float b) {
    unsigned long long r;
    asm("mov.b64 %0, {%1, %2};" : "=l"(r) : "f"(a), "f"(b));
    return r;
}
__device__ __forceinline__ void fma2(unsigned long long& d, unsigned long long a, unsigned long long b) {
    asm("fma.rn.f32x2 %0, %1, %2, %0;" : "+l"(d) : "l"(a), "l"(b));
}
__device__ __forceinline__ unsigned long long add2(unsigned long long a, unsigned long long b) {
    unsigned long long r;
    asm("add.rn.f32x2 %0, %1, %2;" : "=l"(r) : "l"(a), "l"(b));
    return r;
}
__device__ __forceinline__ float2 unpack2(unsigned long long v) {
    float2 f;
    asm("mov.b64 {%0, %1}, %2;" : "=f"(f.x), "=f"(f.y) : "l"(v));
    return f;
}
__device__ __forceinline__ float tanh_fast(float x) {
    float y;
    asm("tanh.approx.f32 %0, %1;" : "=f"(y) : "f"(x));
    return y;
}

template <int HALF>
__device__ __forceinline__ void reduce_round(unsigned long long* a, int lane, int d) {
    const bool hi = (lane & d) != 0;
#pragma unroll
    for (int i = 0; i < HALF; i++) {
        unsigned long long send = hi ? a[i] : a[i + HALF];
        unsigned long long keep = hi ? a[i + HALF] : a[i];
        unsigned long long recv = __shfl_xor_sync(0xffffffffu, send, d);
        a[i] = add2(keep, recv);
    }
}

// ---------------- drive GEMM (+ folded reset): out[bt][r] = X @ [Wfb|Win]^T + b ----
#define DRIVE_SMEM ((64 + 128) * 97 * 4)

__global__ __launch_bounds__(256) void drive_kernel(
    const float* __restrict__ fb, const float* __restrict__ drv,
    const float* __restrict__ Wfb, const float* __restrict__ Win,
    const float* __restrict__ bias, float* __restrict__ out)
{
    extern __shared__ float smem[];
    float (*xs)[97]  = (float (*)[97])smem;              // [64][97]
    float (*wsh)[97] = (float (*)[97])(smem + 64 * 97);  // [128][97]

    const int r0  = blockIdx.x * 128;
    const int bt0 = blockIdx.y * 64;
    const int tid = threadIdx.x;

    // folded reset: 8 blocks (y==0) zero g_h (fp16 zeros); block (0,0) zeroes flags
    if (blockIdx.y == 0) {
        unsigned* p = reinterpret_cast<unsigned*>(&g_h[0][0][0]);
        const int words = 2 * R_ * B_ / 2;   // 8192 uints total
        for (int i = tid; i < words / 8; i += 256) p[blockIdx.x * (words / 8) + i] = 0u;
        if (blockIdx.x == 0 && tid < NBLK) g_flag[tid * 32] = 0u;
    }

    for (int idx = tid; idx < 64 * KTOT; idx += 256) {
        int row = idx / KTOT, col = idx - row * KTOT;
        float v = (col < F_) ? fb[(size_t)(bt0 + row) * F_ + col]
                             : drv[(size_t)(bt0 + row) * I_ + (col - F_)];
        xs[row][col] = v;
    }
    for (int idx = tid; idx < 128 * KTOT; idx += 256) {
        int row = idx / KTOT, col = idx - row * KTOT;
        int r = r0 + row;
        float v = (col < F_) ? Wfb[r * F_ + col] : Win[r * I_ + (col - F_)];
        wsh[row][col] = v;
    }
    __syncthreads();

    const int tx = tid & 15;
    const int ty = tid >> 4;

    float acc[4][8];
#pragma unroll
    for (int i = 0; i < 4; i++)
#pragma unroll
        for (int j = 0; j < 8; j++) acc[i][j] = 0.0f;

    for (int f = 0; f < KTOT; f++) {
        float x0 = xs[ty * 4 + 0][f];
        float x1 = xs[ty * 4 + 1][f];
        float x2 = xs[ty * 4 + 2][f];
        float x3 = xs[ty * 4 + 3][f];
        float w[8];
#pragma unroll
        for (int j = 0; j < 8; j++) w[j] = wsh[tx + 16 * j][f];
#pragma unroll
        for (int j = 0; j < 8; j++) {
            acc[0][j] = fmaf(x0, w[j], acc[0][j]);
            acc[1][j] = fmaf(x1, w[j], acc[1][j]);
            acc[2][j] = fmaf(x2, w[j], acc[2][j]);
            acc[3][j] = fmaf(x3, w[j], acc[3][j]);
        }
    }

#pragma unroll
    for (int j = 0; j < 8; j++) {
        int r = r0 + tx + 16 * j;
        float bv = bias[r];
#pragma unroll
        for (int i = 0; i < 4; i++) {
            size_t bt = (size_t)bt0 + ty * 4 + i;
            out[bt * R_ + r] = acc[i][j] + bv;
        }
    }
}

// ---------------- sequential scan: R6 barrier + smem weights + fp16 h ------------
// thread tid handles k = tid + 256*i (i<4), ALL 8 batches per k.
// weights in smem as duplicated {w,w} pairs: wsh[j][k], 64KB dynamic.
#define SCAN_SMEM (8 * R_ * 8)

__global__ __launch_bounds__(NTHR, 1) void scan_kernel(
    const float* __restrict__ Whh, float* __restrict__ out)
{
    extern __shared__ unsigned long long wsh[];   // [8][1024] {w,w} pairs
    __shared__ float2 partials[8][32];

    const int tid  = threadIdx.x;
    const int lane = tid & 31;
    const int warp = tid >> 5;
    const int r0   = blockIdx.x * 8;

    // fill weight smem: wsh[j*1024 + k] = {w,w}; coalesced reads of Whh
    for (int idx = tid; idx < 8 * R_; idx += NTHR) {
        int j = idx >> 10, k = idx & 1023;
        float w = Whh[(size_t)(r0 + j) * R_ + k];
        wsh[j * R_ + k] = pack2(w, w);
    }
    __syncthreads();

    const float alpha = 0.9f;
    const float onem  = 1.0f - alpha;

    size_t oi0 = 0, oi1 = 0;
    float hprev0 = 0.0f, hprev1 = 0.0f;
    float pv0 = 0.0f, pv1 = 0.0f;        // deferred out-store values
    int er = 0, eb0 = 0;
    if (warp == 0) {
        int j = lane >> 2, p = lane & 3;
        er = r0 + j; eb0 = 2 * p;
        oi0 = ((size_t)eb0 * T_) * R_ + er;
        oi1 = ((size_t)(eb0 + 1) * T_) * R_ + er;
    }

    unsigned* my_flag   = &g_flag[blockIdx.x * 32];
    unsigned* poll_flag = (tid < NBLK) ? &g_flag[tid * 32] : nullptr;

    for (int t = 0; t < T_; t++) {
        const int cur = t & 1, nxt = cur ^ 1;

        // ---- u(t) load + deferred out store: overlap with compute (R6 style) ----
        float u0 = 0.0f, u1 = 0.0f;
        if (warp == 0) {
            u0 = __ldcs(&out[oi0 + (size_t)t * R_]);
            u1 = __ldcs(&out[oi1 + (size_t)t * R_]);
            if (t > 0) {
                __stcg(&out[oi0 + (size_t)(t - 1) * R_], pv0);
                __stcg(&out[oi1 + (size_t)(t - 1) * R_], pv1);
            }
        }

        // ---- load h (fp16, 16B per k = all 8 batches; 4 chunks, MLP=4) ----
        const uint4* hsrc = reinterpret_cast<const uint4*>(&g_h[cur][0][0]);
        uint4 raw[4];
#pragma unroll
        for (int i = 0; i < 4; i++) {
            raw[i] = __ldcg(hsrc + (tid + 256 * i));
        }

        // ---- matvec: 4 k x 8 rows x 4 batch-pairs (f32x2), weights from smem ----
        unsigned long long acc[32];
#pragma unroll
        for (int o = 0; o < 32; o++) acc[o] = 0ull;
#pragma unroll
        for (int i = 0; i < 4; i++) {
            const int k = tid + 256 * i;
            const __half2* hp = reinterpret_cast<const __half2*>(&raw[i]);
            unsigned long long hh[4];
#pragma unroll
            for (int p = 0; p < 4; p++) {
                float2 f = __half22float2(hp[p]);
                hh[p] = pack2(f.x, f.y);
            }
#pragma unroll
            for (int j = 0; j < 8; j++) {
                unsigned long long w = wsh[j * R_ + k];
#pragma unroll
                for (int p = 0; p < 4; p++) {
                    fma2(acc[j * 4 + p], hh[p], w);
                }
            }
        }

        // ---- 5-round log-halving warp reduction over k (32 accs -> 1/lane) ----
        reduce_round<16>(acc, lane, 1);
        reduce_round<8>(acc, lane, 2);
        reduce_round<4>(acc, lane, 4);
        reduce_round<2>(acc, lane, 8);
        reduce_round<1>(acc, lane, 16);

        {
            // lane owns acc index o = 16*b0 + 8*b1 + 4*b2 + 2*b3 + b4 (bits of lane)
            int o = 16 * (lane & 1) + 8 * ((lane >> 1) & 1) + 4 * ((lane >> 2) & 1) +
                    2 * ((lane >> 3) & 1) + ((lane >> 4) & 1);
            partials[warp][o] = unpack2(acc[0]);
        }
        __syncthreads();                                   // (A)

        // ---- epilogue: warp0, tree-add + tanh, h_prev in regs, fp16 publish ----
        if (warp == 0) {
            float2 p0 = partials[0][lane], p1 = partials[1][lane];
            float2 p2 = partials[2][lane], p3 = partials[3][lane];
            float2 p4 = partials[4][lane], p5 = partials[5][lane];
            float2 p6 = partials[6][lane], p7 = partials[7][lane];
            float sx = ((p0.x + p1.x) + (p2.x + p3.x)) + ((p4.x + p5.x) + (p6.x + p7.x));
            float sy = ((p0.y + p1.y) + (p2.y + p3.y)) + ((p4.y + p5.y) + (p6.y + p7.y));

            float v0 = tanh_fast(onem * hprev0 + alpha * (u0 + sx));
            float v1 = tanh_fast(onem * hprev1 + alpha * (u1 + sy));
            __half2 hv = __floats2half2_rn(v0, v1);
            unsigned hb;
            *reinterpret_cast<__half2*>(&hb) = hv;
            __stcg(reinterpret_cast<unsigned*>(&g_h[nxt][er][eb0]), hb);
            hprev0 = v0; hprev1 = v1;
            pv0 = v0; pv1 = v1;

            if (t < T_ - 1) {
                __syncwarp();   // order warp0's g_h stores before lane0's release
                if (lane == 0) {
                    asm volatile("st.release.gpu.global.u32 [%0], %1;"
                                 :: "l"(my_flag), "r"((unsigned)(t + 1)) : "memory");
                }
            }
        }

        if (t < T_ - 1) {
            // ---- wait: thread i acquire-polls CTA i's flag; 128 in parallel ----
            if (tid < NBLK) {
                const unsigned epoch = (unsigned)(t + 1);
                unsigned f;
                do {
                    asm volatile("ld.acquire.gpu.global.u32 %0, [%1];"
                                 : "=r"(f) : "l"(poll_flag) : "memory");
                } while (f < epoch);
            }
            __syncthreads();                               // (C) barrier complete
        }
    }

    // final out store for t = T-1
    if (warp == 0) {
        __stcg(&out[oi0 + (size_t)(T_ - 1) * R_], pv0);
        __stcg(&out[oi1 + (size_t)(T_ - 1) * R_], pv1);
    }
}

// ---------------- launch ----------------
extern "C" void kernel_launch(void* const* d_in, const int* in_sizes, int n_in,
                              void* d_out, int out_size)
{
    (void)in_sizes; (void)n_in; (void)out_size;
    const float* fb   = (const float*)d_in[0];
    const float* drv  = (const float*)d_in[1];
    const float* Wfb  = (const float*)d_in[2];
    const float* Win  = (const float*)d_in[3];
    const float* Whh  = (const float*)d_in[4];
    const float* bias = (const float*)d_in[5];
    float* out = (float*)d_out;

    cudaFuncSetAttribute(drive_kernel, cudaFuncAttributeMaxDynamicSharedMemorySize, DRIVE_SMEM);
    cudaFuncSetAttribute(scan_kernel, cudaFuncAttributeMaxDynamicSharedMemorySize, SCAN_SMEM);

    dim3 dgrid(R_ / 128, (B_ * T_) / 64);
    drive_kernel<<<dgrid, 256, DRIVE_SMEM>>>(fb, drv, Wfb, Win, bias, out);

    scan_kernel<<<NBLK, NTHR, SCAN_SMEM>>>(Whh, out);
}

// round 15
// speedup vs baseline: 1.1016x; 1.1016x over previous
#include <cuda_runtime.h>
#include <cuda_fp16.h>
#include <cstdint>

#define B_    8
#define T_    4096
#define R_    1024
#define F_    64
#define I_    32
#define KTOT  96            // F_ + I_
#define NBLK  128           // scan blocks (8 rows of W_hh each)
#define NTHR  256

// ---------------- device scratch (no allocations allowed) ----------------
// hidden state in fp16: [buf][k][b] — 16B per k row (8 batches)
__device__ __align__(16) __half g_h[2][R_][B_];
__device__ __align__(128) unsigned g_flag[NBLK * 32];  // 1 epoch flag per CTA, private line

// ---------------- helpers ----------------
__device__ __forceinline__ unsigned long long pack2(float a, float b) {
    unsigned long long r;
    asm("mov.b64 %0, {%1, %2};" : "=l"(r) : "f"(a), "f"(b));
    return r;
}
__device__ __forceinline__ void fma2(unsigned long long& d, unsigned long long a, unsigned long long b) {
    asm("fma.rn.f32x2 %0, %1, %2, %0;" : "+l"(d) : "l"(a), "l"(b));
}
__device__ __forceinline__ unsigned long long add2(unsigned long long a, unsigned long long b) {
    unsigned long long r;
    asm("add.rn.f32x2 %0, %1, %2;" : "=l"(r) : "l"(a), "l"(b));
    return r;
}
__device__ __forceinline__ float2 unpack2(unsigned long long v) {
    float2 f;
    asm("mov.b64 {%0, %1}, %2;" : "=f"(f.x), "=f"(f.y) : "l"(v));
    return f;
}
__device__ __forceinline__ float tanh_fast(float x) {
    float y;
    asm("tanh.approx.f32 %0, %1;" : "=f"(y) : "f"(x));
    return y;
}

template <int HALF>
__device__ __forceinline__ void reduce_round(unsigned long long* a, int lane, int d) {
    const bool hi = (lane & d) != 0;
#pragma unroll
    for (int i = 0; i < HALF; i++) {
        unsigned long long send = hi ? a[i] : a[i + HALF];
        unsigned long long keep = hi ? a[i + HALF] : a[i];
        unsigned long long recv = __shfl_xor_sync(0xffffffffu, send, d);
        a[i] = add2(keep, recv);
    }
}

// ---------------- drive GEMM (+ folded reset): out[bt][r] = X @ [Wfb|Win]^T + b ----
#define DRIVE_SMEM ((64 + 128) * 97 * 4)

__global__ __launch_bounds__(256) void drive_kernel(
    const float* __restrict__ fb, const float* __restrict__ drv,
    const float* __restrict__ Wfb, const float* __restrict__ Win,
    const float* __restrict__ bias, float* __restrict__ out)
{
    extern __shared__ float smem[];
    float (*xs)[97]  = (float (*)[97])smem;              // [64][97]
    float (*wsh)[97] = (float (*)[97])(smem + 64 * 97);  // [128][97]

    const int r0  = blockIdx.x * 128;
    const int bt0 = blockIdx.y * 64;
    const int tid = threadIdx.x;

    // folded reset: 8 blocks (y==0) zero g_h (fp16 zeros); block (0,0) zeroes flags
    if (blockIdx.y == 0) {
        unsigned* p = reinterpret_cast<unsigned*>(&g_h[0][0][0]);
        const int words = 2 * R_ * B_ * 2 / 4;   // 8192 uints total
        for (int i = tid; i < words / 8; i += 256) p[blockIdx.x * (words / 8) + i] = 0u;
        if (blockIdx.x == 0 && tid < NBLK) g_flag[tid * 32] = 0u;
    }

    for (int idx = tid; idx < 64 * KTOT; idx += 256) {
        int row = idx / KTOT, col = idx - row * KTOT;
        float v = (col < F_) ? fb[(size_t)(bt0 + row) * F_ + col]
                             : drv[(size_t)(bt0 + row) * I_ + (col - F_)];
        xs[row][col] = v;
    }
    for (int idx = tid; idx < 128 * KTOT; idx += 256) {
        int row = idx / KTOT, col = idx - row * KTOT;
        int r = r0 + row;
        float v = (col < F_) ? Wfb[r * F_ + col] : Win[r * I_ + (col - F_)];
        wsh[row][col] = v;
    }
    __syncthreads();

    const int tx = tid & 15;
    const int ty = tid >> 4;

    float acc[4][8];
#pragma unroll
    for (int i = 0; i < 4; i++)
#pragma unroll
        for (int j = 0; j < 8; j++) acc[i][j] = 0.0f;

    for (int f = 0; f < KTOT; f++) {
        float x0 = xs[ty * 4 + 0][f];
        float x1 = xs[ty * 4 + 1][f];
        float x2 = xs[ty * 4 + 2][f];
        float x3 = xs[ty * 4 + 3][f];
        float w[8];
#pragma unroll
        for (int j = 0; j < 8; j++) w[j] = wsh[tx + 16 * j][f];
#pragma unroll
        for (int j = 0; j < 8; j++) {
            acc[0][j] = fmaf(x0, w[j], acc[0][j]);
            acc[1][j] = fmaf(x1, w[j], acc[1][j]);
            acc[2][j] = fmaf(x2, w[j], acc[2][j]);
            acc[3][j] = fmaf(x3, w[j], acc[3][j]);
        }
    }

#pragma unroll
    for (int j = 0; j < 8; j++) {
        int r = r0 + tx + 16 * j;
        float bv = bias[r];
#pragma unroll
        for (int i = 0; i < 4; i++) {
            size_t bt = (size_t)bt0 + ty * 4 + i;
            out[bt * R_ + r] = acc[i][j] + bv;
        }
    }
}

// ---------------- sequential scan: R6 flow, h in fp16, weights in registers -----
__global__ __launch_bounds__(NTHR, 1) void scan_kernel(
    const float* __restrict__ Whh, float* __restrict__ out)
{
    __shared__ float2 partials[8][32];

    const int tid  = threadIdx.x;
    const int lane = tid & 31;
    const int warp = tid >> 5;
    const int r0   = blockIdx.x * 8;
    const int half = tid & 1;
    const int kq   = tid >> 1;

    // preload W_hh slice, duplicated pairs {w,w} (registers, as in R6)
    unsigned long long wd[8][8];
#pragma unroll
    for (int i = 0; i < 8; i++) {
        int k = kq + i * 128;
#pragma unroll
        for (int j = 0; j < 8; j++) {
            float w = Whh[(size_t)(r0 + j) * R_ + k];
            wd[i][j] = pack2(w, w);
        }
    }

    const float alpha = 0.9f;
    const float onem  = 1.0f - alpha;

    size_t oi0 = 0, oi1 = 0;
    float hprev0 = 0.0f, hprev1 = 0.0f;
    float pv0 = 0.0f, pv1 = 0.0f;        // deferred out-store values
    int er = 0, eb0 = 0;
    if (warp == 0) {
        int j = lane >> 2, p = lane & 3;
        er = r0 + j; eb0 = 2 * p;
        oi0 = ((size_t)eb0 * T_) * R_ + er;
        oi1 = ((size_t)(eb0 + 1) * T_) * R_ + er;
    }

    unsigned* my_flag   = &g_flag[blockIdx.x * 32];
    unsigned* poll_flag = (tid < NBLK) ? &g_flag[tid * 32] : nullptr;

    for (int t = 0; t < T_; t++) {
        const int cur = t & 1, nxt = cur ^ 1;

        // ---- u(t) load + deferred out store: overlap with compute ----
        float u0 = 0.0f, u1 = 0.0f;
        if (warp == 0) {
            u0 = __ldcs(&out[oi0 + (size_t)t * R_]);
            u1 = __ldcs(&out[oi1 + (size_t)t * R_]);
            if (t > 0) {
                __stcg(&out[oi0 + (size_t)(t - 1) * R_], pv0);
                __stcg(&out[oi1 + (size_t)(t - 1) * R_], pv1);
            }
        }

        // ---- load h (fp16: 8B per thread per chunk, MLP=8) ----
        const uint2* hsrc = reinterpret_cast<const uint2*>(&g_h[cur][0][0]);
        uint2 raw[8];
#pragma unroll
        for (int i = 0; i < 8; i++) {
            int k = kq + i * 128;
            raw[i] = __ldcg(hsrc + (k * 2 + half));   // h[k][4*half..4*half+3]
        }

        // ---- partial matvec: 8 k x 8 rows x 4 batches (f32x2) ----
        unsigned long long acc[16];
#pragma unroll
        for (int o = 0; o < 16; o++) acc[o] = 0ull;
#pragma unroll
        for (int i = 0; i < 8; i++) {
            __half2 ha = *reinterpret_cast<__half2*>(&raw[i].x);
            __half2 hb = *reinterpret_cast<__half2*>(&raw[i].y);
            float2 fa = __half22float2(ha);
            float2 fb = __half22float2(hb);
            unsigned long long h01 = pack2(fa.x, fa.y);
            unsigned long long h23 = pack2(fb.x, fb.y);
#pragma unroll
            for (int j = 0; j < 8; j++) {
                fma2(acc[j * 2 + 0], h01, wd[i][j]);
                fma2(acc[j * 2 + 1], h23, wd[i][j]);
            }
        }

        // ---- log-halving warp reduction ----
        reduce_round<8>(acc, lane, 2);
        reduce_round<4>(acc, lane, 4);
        reduce_round<2>(acc, lane, 8);
        reduce_round<1>(acc, lane, 16);

        {
            int o = (((lane >> 1) & 1) << 3) | (((lane >> 2) & 1) << 2) |
                    (((lane >> 3) & 1) << 1) | ((lane >> 4) & 1);
            int j = o >> 1, q = o & 1;
            int p = 2 * half + q;
            partials[warp][j * 4 + p] = unpack2(acc[0]);
        }
        __syncthreads();                                   // (A)

        // ---- epilogue: warp0, tree-add + tanh, h_prev fp32 in regs ----
        if (warp == 0) {
            float2 p0 = partials[0][lane], p1 = partials[1][lane];
            float2 p2 = partials[2][lane], p3 = partials[3][lane];
            float2 p4 = partials[4][lane], p5 = partials[5][lane];
            float2 p6 = partials[6][lane], p7 = partials[7][lane];
            float sx = ((p0.x + p1.x) + (p2.x + p3.x)) + ((p4.x + p5.x) + (p6.x + p7.x));
            float sy = ((p0.y + p1.y) + (p2.y + p3.y)) + ((p4.y + p5.y) + (p6.y + p7.y));

            float v0 = tanh_fast(onem * hprev0 + alpha * (u0 + sx));
            float v1 = tanh_fast(onem * hprev1 + alpha * (u1 + sy));
            __half2 hv = __floats2half2_rn(v0, v1);
            unsigned hb;
            *reinterpret_cast<__half2*>(&hb) = hv;
            __stcg(reinterpret_cast<unsigned*>(&g_h[nxt][er][eb0]), hb);
            hprev0 = v0; hprev1 = v1;
            pv0 = v0; pv1 = v1;

            if (t < T_ - 1) {
                __syncwarp();   // order warp0's g_h stores before lane0's release
                if (lane == 0) {
                    asm volatile("st.release.gpu.global.u32 [%0], %1;"
                                 :: "l"(my_flag), "r"((unsigned)(t + 1)) : "memory");
                }
            }
        }

        if (t < T_ - 1) {
            // ---- wait: thread i acquire-polls CTA i's flag; 128 in parallel ----
            if (tid < NBLK) {
                const unsigned epoch = (unsigned)(t + 1);
                unsigned f;
                do {
                    asm volatile("ld.acquire.gpu.global.u32 %0, [%1];"
                                 : "=r"(f) : "l"(poll_flag) : "memory");
                } while (f < epoch);
            }
            __syncthreads();                               // (C) barrier complete
        }
    }

    // final out store for t = T-1
    if (warp == 0) {
        __stcg(&out[oi0 + (size_t)(T_ - 1) * R_], pv0);
        __stcg(&out[oi1 + (size_t)(T_ - 1) * R_], pv1);
    }
}

// ---------------- launch ----------------
extern "C" void kernel_launch(void* const* d_in, const int* in_sizes, int n_in,
                              void* d_out, int out_size)
{
    (void)in_sizes; (void)n_in; (void)out_size;
    const float* fb   = (const float*)d_in[0];
    const float* drv  = (const float*)d_in[1];
    const float* Wfb  = (const float*)d_in[2];
    const float* Win  = (const float*)d_in[3];
    const float* Whh  = (const float*)d_in[4];
    const float* bias = (const float*)d_in[5];
    float* out = (float*)d_out;

    cudaFuncSetAttribute(drive_kernel, cudaFuncAttributeMaxDynamicSharedMemorySize, DRIVE_SMEM);

    dim3 dgrid(R_ / 128, (B_ * T_) / 64);
    drive_kernel<<<dgrid, 256, DRIVE_SMEM>>>(fb, drv, Wfb, Win, bias, out);

    scan_kernel<<<NBLK, NTHR>>>(Whh, out);
}